// round 2
// baseline (speedup 1.0000x reference)
#include <cuda_runtime.h>
#include <cstdint>

#define L_LEN   65536
#define L_MASK  (L_LEN - 1)
#define CIN     8
#define COUT    8
#define FS      4
#define PP      8        // positions per thread
#define TPB     256      // warps 0-3: co 0-3, warps 4-7: co 4-7 (same positions)

// ---- packed f32x2 helpers (Blackwell sm_100a+) ------------------------------
__device__ __forceinline__ float2 ffma2(float2 a, float2 b, float2 c) {
    float2 d;
    asm("fma.rn.f32x2 %0, %1, %2, %3;"
        : "=l"(reinterpret_cast<unsigned long long&>(d))
        : "l"(reinterpret_cast<const unsigned long long&>(a)),
          "l"(reinterpret_cast<const unsigned long long&>(b)),
          "l"(reinterpret_cast<const unsigned long long&>(c)));
    return d;
}

__device__ __forceinline__ float2 dup2(float x) {
    float2 d;
    asm("mov.b64 %0, {%1, %1};"
        : "=l"(reinterpret_cast<unsigned long long&>(d))
        : "f"(x));
    return d;
}

// ----------------------------------------------------------------------------
// out[b, co, l] = bias[co] + sum_{ci,k} x[b, ci, (l+k) mod L] * W[co, ci, k]
// Thread: one batch b, positions [l0, l0+8), 4 output channels (one co-group).
// Co-group 0/1 live in the same block so duplicated x loads hit L1.
// Double-buffered x prefetch across the ci loop for 2x MLP.
// ----------------------------------------------------------------------------
__global__ __launch_bounds__(TPB)
void conv_pbc_kernel(const float* __restrict__ x,
                     const float* __restrict__ W,
                     const float* __restrict__ bias,
                     float* __restrict__ out)
{
    // packed weights per co-group: w2s[cg][ci][k][cpl] = (W[cg*4+2cpl], W[cg*4+2cpl+1])
    __shared__ float2 w2s[2][CIN][FS][2];
    __shared__ float2 b2s[2][2];

    const int t = threadIdx.x;
    if (t < 128) {                           // 2*8*4*2 = 128 packed entries
        const int cpl = t & 1;
        const int k   = (t >> 1) & 3;
        const int ci  = (t >> 3) & 7;
        const int cg  = (t >> 6) & 1;
        const int co  = cg * 4 + 2 * cpl;
        w2s[cg][ci][k][cpl] = make_float2(W[co * CIN * FS + ci * FS + k],
                                          W[(co + 1) * CIN * FS + ci * FS + k]);
    }
    if (t < 4) {
        const int cg = t >> 1, cpl = t & 1;
        const int co = cg * 4 + 2 * cpl;
        b2s[cg][cpl] = make_float2(bias[co], bias[co + 1]);
    }
    __syncthreads();

    const int cog  = t >> 7;                 // co-group: 0 -> co 0-3, 1 -> co 4-7
    const int l128 = t & 127;
    const int pch  = blockIdx.x * 128 + l128;
    const int b    = pch >> 13;              // 8192 position-chunks per batch
    const int pidx = pch & 8191;
    const int l0   = pidx * PP;

    const float* __restrict__ xb = x + (size_t)b * CIN * L_LEN;
    float* __restrict__ ob =
        out + (size_t)b * COUT * L_LEN + (size_t)(cog * 4) * L_LEN;

    // accumulators: acc[p][cpl] packed over a co-pair, init = bias
    float2 acc[PP][2];
    {
        const float2 c0 = b2s[cog][0], c1 = b2s[cog][1];
        #pragma unroll
        for (int p = 0; p < PP; ++p) { acc[p][0] = c0; acc[p][1] = c1; }
    }

    // fast path iff the 12-float window stays in-bounds (only l0=65528 wraps)
    const bool fast = (l0 + PP + FS <= L_LEN);

    float xv[2][12];                          // double-buffered x window

    // prologue: load ci = 0
    {
        const float* __restrict__ xc = xb;
        if (fast) {
            const float4 a  = *reinterpret_cast<const float4*>(xc + l0);
            const float4 bq = *reinterpret_cast<const float4*>(xc + l0 + 4);
            const float4 cq = *reinterpret_cast<const float4*>(xc + l0 + 8);
            xv[0][0] = a.x;  xv[0][1] = a.y;  xv[0][2]  = a.z;  xv[0][3]  = a.w;
            xv[0][4] = bq.x; xv[0][5] = bq.y; xv[0][6]  = bq.z; xv[0][7]  = bq.w;
            xv[0][8] = cq.x; xv[0][9] = cq.y; xv[0][10] = cq.z; xv[0][11] = cq.w;
        } else {
            #pragma unroll
            for (int i = 0; i < 12; ++i) xv[0][i] = xc[(l0 + i) & L_MASK];
        }
    }

    #pragma unroll
    for (int ci = 0; ci < CIN; ++ci) {
        const int cur = ci & 1;

        // prefetch next ci's window into the other buffer
        if (ci + 1 < CIN) {
            const int nxt = (ci + 1) & 1;
            const float* __restrict__ xc = xb + (size_t)(ci + 1) * L_LEN;
            if (fast) {
                const float4 a  = *reinterpret_cast<const float4*>(xc + l0);
                const float4 bq = *reinterpret_cast<const float4*>(xc + l0 + 4);
                const float4 cq = *reinterpret_cast<const float4*>(xc + l0 + 8);
                xv[nxt][0] = a.x;  xv[nxt][1] = a.y;  xv[nxt][2]  = a.z;  xv[nxt][3]  = a.w;
                xv[nxt][4] = bq.x; xv[nxt][5] = bq.y; xv[nxt][6]  = bq.z; xv[nxt][7]  = bq.w;
                xv[nxt][8] = cq.x; xv[nxt][9] = cq.y; xv[nxt][10] = cq.z; xv[nxt][11] = cq.w;
            } else {
                #pragma unroll
                for (int i = 0; i < 12; ++i) xv[nxt][i] = xc[(l0 + i) & L_MASK];
            }
        }

        // per-ci packed weights for this co-group (broadcast LDS, conflict-free)
        float2 wv[FS][2];
        #pragma unroll
        for (int k = 0; k < FS; ++k) {
            wv[k][0] = w2s[cog][ci][k][0];
            wv[k][1] = w2s[cog][ci][k][1];
        }

        // duplicate x into both f32x2 lanes
        float2 xd[PP + FS - 1];
        #pragma unroll
        for (int i = 0; i < PP + FS - 1; ++i) xd[i] = dup2(xv[cur][i]);

        #pragma unroll
        for (int p = 0; p < PP; ++p) {
            #pragma unroll
            for (int k = 0; k < FS; ++k) {
                const float2 xk = xd[p + k];
                acc[p][0] = ffma2(wv[k][0], xk, acc[p][0]);
                acc[p][1] = ffma2(wv[k][1], xk, acc[p][1]);
            }
        }
    }

    // epilogue: transpose to per-channel float4 runs, vector stores
    #pragma unroll
    for (int cpl = 0; cpl < 2; ++cpl) {
        float* __restrict__ o0 = ob + (size_t)(2 * cpl) * L_LEN + l0;
        float* __restrict__ o1 = o0 + L_LEN;

        float4 v;
        v.x = acc[0][cpl].x; v.y = acc[1][cpl].x; v.z = acc[2][cpl].x; v.w = acc[3][cpl].x;
        *reinterpret_cast<float4*>(o0) = v;
        v.x = acc[4][cpl].x; v.y = acc[5][cpl].x; v.z = acc[6][cpl].x; v.w = acc[7][cpl].x;
        *reinterpret_cast<float4*>(o0 + 4) = v;

        v.x = acc[0][cpl].y; v.y = acc[1][cpl].y; v.z = acc[2][cpl].y; v.w = acc[3][cpl].y;
        *reinterpret_cast<float4*>(o1) = v;
        v.x = acc[4][cpl].y; v.y = acc[5][cpl].y; v.z = acc[6][cpl].y; v.w = acc[7][cpl].y;
        *reinterpret_cast<float4*>(o1 + 4) = v;
    }
}

extern "C" void kernel_launch(void* const* d_in, const int* in_sizes, int n_in,
                              void* d_out, int out_size)
{
    const float* x    = (const float*)d_in[0];  // (64, 8, 65536)
    const float* W    = (const float*)d_in[1];  // (8, 8, 4)
    const float* bias = (const float*)d_in[2];  // (8,)
    float* out        = (float*)d_out;          // (64, 8, 65536)

    // 64 batches * 8192 position-chunks * 2 co-groups = 1.05M threads
    const int n_blocks = 64 * (L_LEN / PP) / 128;   // 4096 blocks of 256
    conv_pbc_kernel<<<n_blocks, TPB>>>(x, W, bias, out);
}

// round 3
// speedup vs baseline: 1.9545x; 1.9545x over previous
#include <cuda_runtime.h>
#include <cstdint>

#define L_LEN   65536
#define L_MASK  (L_LEN - 1)
#define CIN     8
#define COUT    8
#define FS      4
#define PP      8        // positions per thread
#define TPB     128

// ---- packed f32x2 helpers (Blackwell sm_100a+) ------------------------------
__device__ __forceinline__ float2 ffma2(float2 a, float2 b, float2 c) {
    float2 d;
    asm("fma.rn.f32x2 %0, %1, %2, %3;"
        : "=l"(reinterpret_cast<unsigned long long&>(d))
        : "l"(reinterpret_cast<const unsigned long long&>(a)),
          "l"(reinterpret_cast<const unsigned long long&>(b)),
          "l"(reinterpret_cast<const unsigned long long&>(c)));
    return d;
}

__device__ __forceinline__ float2 dup2(float x) {
    float2 d;
    asm("mov.b64 %0, {%1, %1};"
        : "=l"(reinterpret_cast<unsigned long long&>(d))
        : "f"(x));
    return d;
}

// ----------------------------------------------------------------------------
// out[b, co, l] = bias[co] + sum_{ci,k} x[b, ci, (l+k) mod L] * W[co, ci, k]
// Thread: one batch b, positions [l0, l0+8), ALL 8 output channels
// (4 co-pairs packed in f32x2). The ci loop is software-pipelined 2 deep:
// a 3-slot ring of 12-float x windows keeps 6 LDG.128s in flight per thread.
// ----------------------------------------------------------------------------
__global__ __launch_bounds__(TPB, 3)
void conv_pbc_kernel(const float* __restrict__ x,
                     const float* __restrict__ W,
                     const float* __restrict__ bias,
                     float* __restrict__ out)
{
    // packed weights: w2s[ci][k][cp] = (W[2cp, ci, k], W[2cp+1, ci, k])
    __shared__ float2 w2s[CIN][FS][COUT / 2];
    __shared__ float2 b2s[COUT / 2];

    const int t = threadIdx.x;
    if (t < CIN * FS * (COUT / 2)) {         // 128 entries, one per thread
        const int cp = t & 3;
        const int k  = (t >> 2) & 3;
        const int ci = (t >> 4) & 7;
        w2s[ci][k][cp] = make_float2(W[(2 * cp)     * CIN * FS + ci * FS + k],
                                     W[(2 * cp + 1) * CIN * FS + ci * FS + k]);
    }
    if (t < COUT / 2)
        b2s[t] = make_float2(bias[2 * t], bias[2 * t + 1]);
    __syncthreads();

    const int gtid = blockIdx.x * TPB + t;
    const int b    = gtid >> 13;             // 8192 threads per batch (L/PP)
    const int pidx = gtid & 8191;
    const int l0   = pidx * PP;

    const float* __restrict__ xb = x   + (size_t)b * CIN  * L_LEN;
    float*       __restrict__ ob = out + (size_t)b * COUT * L_LEN;

    // accumulators: acc[p][cp] = f32x2 over the co-pair, init = bias
    float2 acc[PP][4];
    {
        const float2 c0 = b2s[0], c1 = b2s[1], c2 = b2s[2], c3 = b2s[3];
        #pragma unroll
        for (int p = 0; p < PP; ++p) {
            acc[p][0] = c0; acc[p][1] = c1; acc[p][2] = c2; acc[p][3] = c3;
        }
    }

    // fast path iff the 12-float window [l0, l0+12) stays in-bounds;
    // only the last thread per batch (l0 = 65528) wraps.
    const bool fast = (l0 + PP + FS <= L_LEN);

    float xv[3][12];                          // 3-slot ring of x windows

    // load one ci's 12-float window into ring slot s
    auto load_win = [&](int ci, int s) {
        const float* __restrict__ xc = xb + (size_t)ci * L_LEN;
        if (fast) {
            const float4 a  = *reinterpret_cast<const float4*>(xc + l0);
            const float4 bq = *reinterpret_cast<const float4*>(xc + l0 + 4);
            const float4 cq = *reinterpret_cast<const float4*>(xc + l0 + 8);
            xv[s][0] = a.x;  xv[s][1] = a.y;  xv[s][2]  = a.z;  xv[s][3]  = a.w;
            xv[s][4] = bq.x; xv[s][5] = bq.y; xv[s][6]  = bq.z; xv[s][7]  = bq.w;
            xv[s][8] = cq.x; xv[s][9] = cq.y; xv[s][10] = cq.z; xv[s][11] = cq.w;
        } else {
            #pragma unroll
            for (int i = 0; i < 12; ++i)
                xv[s][i] = xc[(l0 + i) & L_MASK];
        }
    };

    // prologue: prefetch ci = 0, 1
    load_win(0, 0);
    load_win(1, 1);

    #pragma unroll
    for (int ci = 0; ci < CIN; ++ci) {
        // prefetch ci+2 into the slot being vacated two iterations ahead
        if (ci + 2 < CIN)
            load_win(ci + 2, (ci + 2) % 3);

        const int cur = ci % 3;

        // per-ci packed weights (broadcast LDS, conflict-free)
        float2 wv[FS][4];
        #pragma unroll
        for (int k = 0; k < FS; ++k)
            #pragma unroll
            for (int cp = 0; cp < 4; ++cp)
                wv[k][cp] = w2s[ci][k][cp];

        // duplicate x into both f32x2 lanes (one MOV pair each)
        float2 xd[PP + FS - 1];
        #pragma unroll
        for (int i = 0; i < PP + FS - 1; ++i)
            xd[i] = dup2(xv[cur][i]);

        #pragma unroll
        for (int p = 0; p < PP; ++p) {
            #pragma unroll
            for (int k = 0; k < FS; ++k) {
                const float2 xk = xd[p + k];
                #pragma unroll
                for (int cp = 0; cp < 4; ++cp)
                    acc[p][cp] = ffma2(wv[k][cp], xk, acc[p][cp]);
            }
        }
    }

    // epilogue: transpose to per-channel float4 runs, vector stores
    #pragma unroll
    for (int cp = 0; cp < 4; ++cp) {
        float* __restrict__ o0 = ob + (size_t)(2 * cp)     * L_LEN + l0;
        float* __restrict__ o1 = o0 + L_LEN;

        float4 v;
        v.x = acc[0][cp].x; v.y = acc[1][cp].x; v.z = acc[2][cp].x; v.w = acc[3][cp].x;
        *reinterpret_cast<float4*>(o0) = v;
        v.x = acc[4][cp].x; v.y = acc[5][cp].x; v.z = acc[6][cp].x; v.w = acc[7][cp].x;
        *reinterpret_cast<float4*>(o0 + 4) = v;

        v.x = acc[0][cp].y; v.y = acc[1][cp].y; v.z = acc[2][cp].y; v.w = acc[3][cp].y;
        *reinterpret_cast<float4*>(o1) = v;
        v.x = acc[4][cp].y; v.y = acc[5][cp].y; v.z = acc[6][cp].y; v.w = acc[7][cp].y;
        *reinterpret_cast<float4*>(o1 + 4) = v;
    }
}

extern "C" void kernel_launch(void* const* d_in, const int* in_sizes, int n_in,
                              void* d_out, int out_size)
{
    const float* x    = (const float*)d_in[0];  // (64, 8, 65536)
    const float* W    = (const float*)d_in[1];  // (8, 8, 4)
    const float* bias = (const float*)d_in[2];  // (8,)
    float* out        = (float*)d_out;          // (64, 8, 65536)

    // total threads = 64 batches * (65536/8) = 524288 -> 4096 blocks of 128
    const int n_threads = 64 * (L_LEN / PP);
    const int n_blocks  = n_threads / TPB;
    conv_pbc_kernel<<<n_blocks, TPB>>>(x, W, bias, out);
}

// round 4
// speedup vs baseline: 2.1474x; 1.0987x over previous
#include <cuda_runtime.h>
#include <cstdint>

#define L_LEN   65536
#define L_MASK  (L_LEN - 1)
#define CIN     8
#define COUT    8
#define FS      4
#define TPB     128
#define TILE    1024            // positions per block
#define ROWF    1028            // smem row floats (1024 + 4 halo), 16B-aligned

// ---- packed f32x2 helpers (Blackwell sm_100a+) ------------------------------
__device__ __forceinline__ float2 ffma2(float2 a, float2 b, float2 c) {
    float2 d;
    asm("fma.rn.f32x2 %0, %1, %2, %3;"
        : "=l"(reinterpret_cast<unsigned long long&>(d))
        : "l"(reinterpret_cast<const unsigned long long&>(a)),
          "l"(reinterpret_cast<const unsigned long long&>(b)),
          "l"(reinterpret_cast<const unsigned long long&>(c)));
    return d;
}

__device__ __forceinline__ float2 dup2(float x) {
    float2 d;
    asm("mov.b64 %0, {%1, %1};"
        : "=l"(reinterpret_cast<unsigned long long&>(d))
        : "f"(x));
    return d;
}

// ----------------------------------------------------------------------------
// out[b, co, l] = bias[co] + sum_{ci,k} x[b, ci, (l+k) mod L] * W[co, ci, k]
//
// Block: one batch b, 1024 consecutive positions, all ci staged in SMEM.
// Phase 1: burst-load x tile (16 coalesced LDG.128/thread in flight) + halo.
// Phase 2: compute from SMEM. Thread t owns two 4-position bundles at
//          4t and 4t+512 -> conflict-free LDS.128 windows (16B lane stride)
//          and perfectly coalesced STG.128 epilogue.
// ----------------------------------------------------------------------------
__global__ __launch_bounds__(TPB, 4)
void conv_pbc_kernel(const float* __restrict__ x,
                     const float* __restrict__ W,
                     const float* __restrict__ bias,
                     float* __restrict__ out)
{
    __shared__ float  xs[CIN][ROWF];
    __shared__ float2 w2s[CIN][FS][COUT / 2];   // (W[2cp,ci,k], W[2cp+1,ci,k])
    __shared__ float2 b2s[COUT / 2];

    const int t = threadIdx.x;

    // ---- weights / bias into SMEM (128 packed entries, one per thread) ----
    {
        const int cp = t & 3;
        const int k  = (t >> 2) & 3;
        const int ci = (t >> 4) & 7;
        w2s[ci][k][cp] = make_float2(W[(2 * cp)     * CIN * FS + ci * FS + k],
                                     W[(2 * cp + 1) * CIN * FS + ci * FS + k]);
    }
    if (t < COUT / 2)
        b2s[t] = make_float2(bias[2 * t], bias[2 * t + 1]);

    const int b    = blockIdx.x >> 6;          // 64 chunks per batch
    const int base = (blockIdx.x & 63) << 10;  // chunk * 1024

    const float* __restrict__ xb = x + (size_t)b * CIN * L_LEN;

    // ---- phase 1: stage x tile (all LDGs issued before any STS) ----
    float4 va[CIN], vb[CIN], vh;
    #pragma unroll
    for (int ci = 0; ci < CIN; ++ci) {
        const float4* __restrict__ xc4 =
            reinterpret_cast<const float4*>(xb + (size_t)ci * L_LEN + base);
        va[ci] = xc4[t];
        vb[ci] = xc4[t + 128];
    }
    if (t < CIN) {   // halo: 4 floats past the tile, circular (always aligned)
        const float* __restrict__ xc = xb + (size_t)t * L_LEN;
        vh = *reinterpret_cast<const float4*>(xc + ((base + TILE) & L_MASK));
    }
    #pragma unroll
    for (int ci = 0; ci < CIN; ++ci) {
        *reinterpret_cast<float4*>(&xs[ci][4 * t])       = va[ci];
        *reinterpret_cast<float4*>(&xs[ci][512 + 4 * t]) = vb[ci];
    }
    if (t < CIN)
        *reinterpret_cast<float4*>(&xs[t][TILE]) = vh;
    __syncthreads();

    // ---- accumulators: acc[bundle][q][cp], init = bias ----
    float2 acc[2][4][COUT / 2];
    {
        const float2 c0 = b2s[0], c1 = b2s[1], c2 = b2s[2], c3 = b2s[3];
        #pragma unroll
        for (int j = 0; j < 2; ++j)
            #pragma unroll
            for (int q = 0; q < 4; ++q) {
                acc[j][q][0] = c0; acc[j][q][1] = c1;
                acc[j][q][2] = c2; acc[j][q][3] = c3;
            }
    }

    // ---- phase 2: compute from SMEM ----
    #pragma unroll
    for (int ci = 0; ci < CIN; ++ci) {
        // packed weights for this ci (broadcast LDS, conflict-free)
        float2 wv[FS][COUT / 2];
        #pragma unroll
        for (int k = 0; k < FS; ++k)
            #pragma unroll
            for (int cp = 0; cp < 4; ++cp)
                wv[k][cp] = w2s[ci][k][cp];

        // two 8-float windows, each two conflict-free LDS.128
        float xw[2][8];
        {
            const float4 a0 = *reinterpret_cast<const float4*>(&xs[ci][4 * t]);
            const float4 a1 = *reinterpret_cast<const float4*>(&xs[ci][4 * t + 4]);
            const float4 b0 = *reinterpret_cast<const float4*>(&xs[ci][512 + 4 * t]);
            const float4 b1 = *reinterpret_cast<const float4*>(&xs[ci][512 + 4 * t + 4]);
            xw[0][0] = a0.x; xw[0][1] = a0.y; xw[0][2] = a0.z; xw[0][3] = a0.w;
            xw[0][4] = a1.x; xw[0][5] = a1.y; xw[0][6] = a1.z; xw[0][7] = a1.w;
            xw[1][0] = b0.x; xw[1][1] = b0.y; xw[1][2] = b0.z; xw[1][3] = b0.w;
            xw[1][4] = b1.x; xw[1][5] = b1.y; xw[1][6] = b1.z; xw[1][7] = b1.w;
        }

        // dup2 each window value once; fan out to all (q, k) with q = i - k
        #pragma unroll
        for (int j = 0; j < 2; ++j) {
            #pragma unroll
            for (int i = 0; i < 7; ++i) {
                const float2 xk = dup2(xw[j][i]);
                #pragma unroll
                for (int k = 0; k < FS; ++k) {
                    const int q = i - k;
                    if (q >= 0 && q < 4) {
                        #pragma unroll
                        for (int cp = 0; cp < 4; ++cp)
                            acc[j][q][cp] = ffma2(wv[k][cp], xk, acc[j][q][cp]);
                    }
                }
            }
        }
    }

    // ---- epilogue: coalesced STG.128 per (co, bundle) ----
    float* __restrict__ ob = out + (size_t)b * COUT * L_LEN + base;
    #pragma unroll
    for (int cp = 0; cp < 4; ++cp) {
        #pragma unroll
        for (int j = 0; j < 2; ++j) {
            float4 v;
            v.x = acc[j][0][cp].x; v.y = acc[j][1][cp].x;
            v.z = acc[j][2][cp].x; v.w = acc[j][3][cp].x;
            *reinterpret_cast<float4*>(ob + (size_t)(2 * cp) * L_LEN + 512 * j + 4 * t) = v;
            v.x = acc[j][0][cp].y; v.y = acc[j][1][cp].y;
            v.z = acc[j][2][cp].y; v.w = acc[j][3][cp].y;
            *reinterpret_cast<float4*>(ob + (size_t)(2 * cp + 1) * L_LEN + 512 * j + 4 * t) = v;
        }
    }
}

extern "C" void kernel_launch(void* const* d_in, const int* in_sizes, int n_in,
                              void* d_out, int out_size)
{
    const float* x    = (const float*)d_in[0];  // (64, 8, 65536)
    const float* W    = (const float*)d_in[1];  // (8, 8, 4)
    const float* bias = (const float*)d_in[2];  // (8,)
    float* out        = (float*)d_out;          // (64, 8, 65536)

    // 64 batches * 64 position-chunks = 4096 blocks of 128
    conv_pbc_kernel<<<64 * (L_LEN / TILE), TPB>>>(x, W, bias, out);
}